// round 1
// baseline (speedup 1.0000x reference)
#include <cuda_runtime.h>
#include <cuda_bf16.h>
#include <math.h>

// Problem constants (fixed shapes from reference)
#define S_LEN 1024
#define BATCH 8
#define EMB   1024
#define HEADS 16
#define HDIM  64
#define MROWS (S_LEN * BATCH)   // 8192
#define F3    (3 * EMB)          // 3072

// -------- scratch (static device allocations; no cudaMalloc allowed) --------
__device__ float g_qkv[MROWS * F3];      // (S,B,3E)  ~100.7 MB
__device__ float g_ctx[MROWS * EMB];     // (S,B,E)   ~33.6 MB
__device__ float g_ao [MROWS * EMB];     // (S,B,E)   ~33.6 MB
__device__ float g_colsum[BATCH * S_LEN]; // per-(b,t) sum of attn probs over (h,s)

// ---------------------------------------------------------------------------
// zero kernel: colsum + output
// ---------------------------------------------------------------------------
__global__ void zero_kernel(float* out) {
    int i = blockIdx.x * 256 + threadIdx.x;
    if (i < BATCH * S_LEN) { g_colsum[i] = 0.0f; }
    if (i < BATCH * EMB)   { out[i] = 0.0f; }
}

// ---------------------------------------------------------------------------
// SGEMM: C[m][n] = sum_k A[m][k] * B[n][k] + bias[n]
// A: [M,K] row-major, B: [N,K] row-major (i.e. C = A * B^T)
// 64x64 tile, BK=32, 256 threads, 4x4 per-thread micro-tile.
// M,N,K all multiples of tile sizes (no bounds checks).
// ---------------------------------------------------------------------------
#define BM 64
#define BN 64
#define BK 32

__global__ __launch_bounds__(256) void sgemm_bias(
    const float* __restrict__ A, const float* __restrict__ Bm,
    const float* __restrict__ bias, float* __restrict__ C,
    int M, int N, int K)
{
    __shared__ float As[BK][BM + 1];
    __shared__ float Bs[BK][BN + 1];

    int tid = threadIdx.x;
    int tx = tid & 15;          // 0..15 -> n
    int ty = tid >> 4;          // 0..15 -> m
    int m0 = blockIdx.y * BM;
    int n0 = blockIdx.x * BN;

    float acc[4][4] = {};

    for (int k0 = 0; k0 < K; k0 += BK) {
        // load A tile (BM x BK): consecutive tid -> consecutive k (coalesced rows)
        #pragma unroll
        for (int idx = tid; idx < BM * BK; idx += 256) {
            int r  = idx / BK;
            int kk = idx % BK;
            As[kk][r] = A[(size_t)(m0 + r) * K + k0 + kk];
        }
        #pragma unroll
        for (int idx = tid; idx < BN * BK; idx += 256) {
            int r  = idx / BK;
            int kk = idx % BK;
            Bs[kk][r] = Bm[(size_t)(n0 + r) * K + k0 + kk];
        }
        __syncthreads();

        #pragma unroll
        for (int kk = 0; kk < BK; kk++) {
            float a[4], b[4];
            #pragma unroll
            for (int i = 0; i < 4; i++) a[i] = As[kk][ty * 4 + i];
            #pragma unroll
            for (int j = 0; j < 4; j++) b[j] = Bs[kk][tx * 4 + j];
            #pragma unroll
            for (int i = 0; i < 4; i++)
                #pragma unroll
                for (int j = 0; j < 4; j++)
                    acc[i][j] = fmaf(a[i], b[j], acc[i][j]);
        }
        __syncthreads();
    }

    #pragma unroll
    for (int i = 0; i < 4; i++) {
        int m = m0 + ty * 4 + i;
        #pragma unroll
        for (int j = 0; j < 4; j++) {
            int n = n0 + tx * 4 + j;
            C[(size_t)m * N + n] = acc[i][j] + bias[n];
        }
    }
}

// ---------------------------------------------------------------------------
// Flash attention per (b, h, 64-row s-block):
//  - online softmax over 16 t-tiles of 64
//  - ctx = softmax(QK^T * scale) @ V, written to g_ctx (S,B,E)
//  - second pass: recompute probs with final (m,l), accumulate column sums
//    into g_colsum[b][t] via atomics (needed for the pooled output).
// Dynamic smem: Qs/Ks/Vs/Ps 64x65 fp32 + 3x64 stats = 67328 bytes.
// ---------------------------------------------------------------------------
#define ATTN_SMEM_BYTES ((4 * 64 * 65 + 3 * 64) * 4)

__global__ __launch_bounds__(256) void attn_kernel(
    const float* __restrict__ qkv, float* __restrict__ ctx,
    float* __restrict__ colsum)
{
    extern __shared__ float sm[];
    float* Qs   = sm;
    float* Ks   = Qs + 64 * 65;
    float* Vs   = Ks + 64 * 65;
    float* Ps   = Vs + 64 * 65;
    float* mrow = Ps + 64 * 65;
    float* lrow = mrow + 64;
    float* crow = lrow + 64;

    const int tid = threadIdx.x;
    const int tx = tid & 15;
    const int ty = tid >> 4;
    const int b  = blockIdx.z;
    const int h  = blockIdx.y;
    const int s0 = blockIdx.x * 64;
    const float scale = 0.125f;  // 1/sqrt(64)

    // load Q tile
    #pragma unroll
    for (int idx = tid; idx < 64 * 64; idx += 256) {
        int r = idx >> 6, d = idx & 63;
        Qs[r * 65 + d] = qkv[((size_t)(s0 + r) * BATCH + b) * F3 + h * HDIM + d];
    }
    if (tid < 64) { mrow[tid] = -1e30f; lrow[tid] = 0.0f; }

    float acc[4][4] = {};
    __syncthreads();

    // ---- main flash loop ----
    for (int tb = 0; tb < 16; tb++) {
        int t0 = tb * 64;
        #pragma unroll
        for (int idx = tid; idx < 64 * 64; idx += 256) {
            int r = idx >> 6, d = idx & 63;
            const float* base = qkv + ((size_t)(t0 + r) * BATCH + b) * F3 + h * HDIM + d;
            Ks[r * 65 + d] = base[EMB];
            Vs[r * 65 + d] = base[2 * EMB];
        }
        __syncthreads();

        // S = scale * Q K^T (64x64), 4x4 per thread
        float sreg[4][4] = {};
        #pragma unroll 8
        for (int d = 0; d < 64; d++) {
            float a[4], kk[4];
            #pragma unroll
            for (int i = 0; i < 4; i++) a[i]  = Qs[(ty * 4 + i) * 65 + d];
            #pragma unroll
            for (int j = 0; j < 4; j++) kk[j] = Ks[(tx * 4 + j) * 65 + d];
            #pragma unroll
            for (int i = 0; i < 4; i++)
                #pragma unroll
                for (int j = 0; j < 4; j++)
                    sreg[i][j] = fmaf(a[i], kk[j], sreg[i][j]);
        }
        #pragma unroll
        for (int i = 0; i < 4; i++)
            #pragma unroll
            for (int j = 0; j < 4; j++)
                Ps[(ty * 4 + i) * 65 + tx * 4 + j] = sreg[i][j] * scale;
        __syncthreads();

        // online softmax: one thread per row
        if (tid < 64) {
            int i = tid;
            float mo = mrow[i];
            float mx = mo;
            #pragma unroll 8
            for (int j = 0; j < 64; j++) mx = fmaxf(mx, Ps[i * 65 + j]);
            float corr = __expf(mo - mx);
            float psum = 0.0f;
            #pragma unroll 8
            for (int j = 0; j < 64; j++) {
                float p = __expf(Ps[i * 65 + j] - mx);
                Ps[i * 65 + j] = p;
                psum += p;
            }
            lrow[i] = lrow[i] * corr + psum;
            mrow[i] = mx;
            crow[i] = corr;
        }
        __syncthreads();

        // rescale + accumulate P @ V (thread owns rows ty*4+i, d-cols tx*4+j)
        #pragma unroll
        for (int i = 0; i < 4; i++) {
            float c = crow[ty * 4 + i];
            #pragma unroll
            for (int j = 0; j < 4; j++) acc[i][j] *= c;
        }
        #pragma unroll 8
        for (int jj = 0; jj < 64; jj++) {
            float p[4], v[4];
            #pragma unroll
            for (int i = 0; i < 4; i++) p[i] = Ps[(ty * 4 + i) * 65 + jj];
            #pragma unroll
            for (int j = 0; j < 4; j++) v[j] = Vs[jj * 65 + tx * 4 + j];
            #pragma unroll
            for (int i = 0; i < 4; i++)
                #pragma unroll
                for (int j = 0; j < 4; j++)
                    acc[i][j] = fmaf(p[i], v[j], acc[i][j]);
        }
        __syncthreads();
    }

    // write normalized ctx
    #pragma unroll
    for (int i = 0; i < 4; i++) {
        int r = ty * 4 + i;
        float inv_l = 1.0f / lrow[r];
        #pragma unroll
        for (int j = 0; j < 4; j++) {
            int d = tx * 4 + j;
            ctx[((size_t)(s0 + r) * BATCH + b) * EMB + h * HDIM + d] = acc[i][j] * inv_l;
        }
    }

    // ---- colsum pass: recompute probs with final (m,l), sum over rows ----
    for (int tb = 0; tb < 16; tb++) {
        int t0 = tb * 64;
        #pragma unroll
        for (int idx = tid; idx < 64 * 64; idx += 256) {
            int r = idx >> 6, d = idx & 63;
            Ks[r * 65 + d] = qkv[((size_t)(t0 + r) * BATCH + b) * F3 + EMB + h * HDIM + d];
        }
        __syncthreads();

        float sreg[4][4] = {};
        #pragma unroll 8
        for (int d = 0; d < 64; d++) {
            float a[4], kk[4];
            #pragma unroll
            for (int i = 0; i < 4; i++) a[i]  = Qs[(ty * 4 + i) * 65 + d];
            #pragma unroll
            for (int j = 0; j < 4; j++) kk[j] = Ks[(tx * 4 + j) * 65 + d];
            #pragma unroll
            for (int i = 0; i < 4; i++)
                #pragma unroll
                for (int j = 0; j < 4; j++)
                    sreg[i][j] = fmaf(a[i], kk[j], sreg[i][j]);
        }
        #pragma unroll
        for (int i = 0; i < 4; i++) {
            int r = ty * 4 + i;
            float m = mrow[r];
            float inv_l = 1.0f / lrow[r];
            #pragma unroll
            for (int j = 0; j < 4; j++)
                Ps[r * 65 + tx * 4 + j] = __expf(sreg[i][j] * scale - m) * inv_l;
        }
        __syncthreads();

        if (tid < 64) {
            int j = tid;
            float cs = 0.0f;
            #pragma unroll 8
            for (int i = 0; i < 64; i++) cs += Ps[i * 65 + j];
            atomicAdd(&colsum[b * S_LEN + t0 + j], cs);
        }
        // next iteration's Ks load races only with this iteration's sreg
        // (Ks reads), which completed before the __syncthreads above.
        __syncthreads();
    }
}

// ---------------------------------------------------------------------------
// pooled[b,e] = sum_t (colsum[b,t] / (S*H)) * AO[t,b,e]
// grid (16 t-chunks of 64, B); 256 threads each covering 4 e's; atomic combine.
// ---------------------------------------------------------------------------
__global__ __launch_bounds__(256) void pool_kernel(
    const float* __restrict__ AO, const float* __restrict__ colsum,
    float* __restrict__ out)
{
    int b = blockIdx.y;
    int t0 = blockIdx.x * 64;
    float accv[4] = {0.f, 0.f, 0.f, 0.f};
    const float inv = 1.0f / ((float)S_LEN * (float)HEADS);
    for (int t = t0; t < t0 + 64; t++) {
        float w = colsum[b * S_LEN + t] * inv;
        const float* row = AO + ((size_t)t * BATCH + b) * EMB;
        #pragma unroll
        for (int k = 0; k < 4; k++)
            accv[k] = fmaf(w, row[threadIdx.x + k * 256], accv[k]);
    }
    #pragma unroll
    for (int k = 0; k < 4; k++)
        atomicAdd(&out[b * EMB + threadIdx.x + k * 256], accv[k]);
}

// ---------------------------------------------------------------------------
// launch
// ---------------------------------------------------------------------------
extern "C" void kernel_launch(void* const* d_in, const int* in_sizes, int n_in,
                              void* d_out, int out_size)
{
    const float* x     = (const float*)d_in[0];
    const float* w_in  = (const float*)d_in[1];
    const float* b_in  = (const float*)d_in[2];
    const float* w_out = (const float*)d_in[3];
    const float* b_out = (const float*)d_in[4];
    float* out = (float*)d_out;

    float *qkv_p, *ctx_p, *ao_p, *colsum_p;
    cudaGetSymbolAddress((void**)&qkv_p,    g_qkv);
    cudaGetSymbolAddress((void**)&ctx_p,    g_ctx);
    cudaGetSymbolAddress((void**)&ao_p,     g_ao);
    cudaGetSymbolAddress((void**)&colsum_p, g_colsum);

    cudaFuncSetAttribute(attn_kernel, cudaFuncAttributeMaxDynamicSharedMemorySize,
                         ATTN_SMEM_BYTES);

    // 1) zero colsum + output
    zero_kernel<<<(BATCH * S_LEN + 255) / 256, 256>>>(out);

    // 2) QKV projection: (8192 x 3072) = x (8192 x 1024) @ w_in^T
    sgemm_bias<<<dim3(F3 / BN, MROWS / BM), 256>>>(x, w_in, b_in, qkv_p,
                                                   MROWS, F3, EMB);

    // 3) attention (ctx + colsum)
    attn_kernel<<<dim3(S_LEN / 64, HEADS, BATCH), 256, ATTN_SMEM_BYTES>>>(
        qkv_p, ctx_p, colsum_p);

    // 4) output projection: (8192 x 1024) = ctx @ w_out^T
    sgemm_bias<<<dim3(EMB / BN, MROWS / BM), 256>>>(ctx_p, w_out, b_out, ao_p,
                                                    MROWS, EMB, EMB);

    // 5) weighted pooling into d_out
    pool_kernel<<<dim3(S_LEN / 64, BATCH), 256>>>(ao_p, colsum_p, out);
}

// round 2
// speedup vs baseline: 1.5734x; 1.5734x over previous
#include <cuda_runtime.h>
#include <cuda_bf16.h>
#include <math.h>

// Problem constants (fixed shapes)
#define S_LEN 1024
#define BATCH 8
#define EMB   1024
#define HEADS 16
#define HDIM  64
#define MROWS (S_LEN * BATCH)   // 8192
#define F3    (3 * EMB)         // 3072
#define NSB   (S_LEN / 128)     // 8 s-blocks per (b,h)
#define NCTA  (BATCH * HEADS * NSB)  // 1024 attention CTAs
#define NTILE 16                // 1024/64 t-tiles

// -------- scratch (__device__ globals; no cudaMalloc allowed) --------
__device__ float g_qkv[MROWS * F3];          // (S,B,3E)
__device__ float g_ctx[MROWS * EMB];         // (S,B,E)
__device__ float g_ao [MROWS * EMB];         // (S,B,E)
__device__ float g_colsum[BATCH * S_LEN];
__device__ float g_ps[(size_t)NCTA * NTILE * 64 * 128];  // unnormalized probs, [cta][tile][t][row]
__device__ float g_mrun[NCTA * NTILE * 128];             // running max after each tile
__device__ float g_lf[NCTA * 128];                       // final l per row

// ---------------------------------------------------------------------------
__global__ void zero_kernel(float* out) {
    int i = blockIdx.x * 256 + threadIdx.x;
    if (i < BATCH * S_LEN) g_colsum[i] = 0.0f;
    if (i < BATCH * EMB)   out[i] = 0.0f;
}

// ---------------------------------------------------------------------------
// SGEMM: C[m][n] = sum_k A[m][k]*B[n][k] + bias[n]   (C = A * B^T)
// 128x128 tile, BK=16, 256 threads, 8x8 micro-tile, double-buffered.
// ---------------------------------------------------------------------------
#define GBM 128
#define GBN 128
#define GBK 16
#define GPAD 4
#define GLDA (GBM + GPAD)

__global__ __launch_bounds__(256) void sgemm_bias(
    const float* __restrict__ A, const float* __restrict__ Bm,
    const float* __restrict__ bias, float* __restrict__ C,
    int M, int N, int K)
{
    __shared__ __align__(16) float As[2][GBK][GLDA];
    __shared__ __align__(16) float Bs[2][GBK][GLDA];

    const int tid = threadIdx.x;
    const int tx = tid & 15;
    const int ty = tid >> 4;
    const int m0 = blockIdx.y * GBM;
    const int n0 = blockIdx.x * GBN;

    const int lr = tid >> 2;          // 0..63
    const int lk = (tid & 3) << 2;    // 0,4,8,12

    const float* Ap = A + (size_t)(m0 + lr) * K + lk;
    const float* Bp = Bm + (size_t)(n0 + lr) * K + lk;
    const size_t rowK = (size_t)64 * K;

    float4 pa0 = *(const float4*)(Ap);
    float4 pa1 = *(const float4*)(Ap + rowK);
    float4 pb0 = *(const float4*)(Bp);
    float4 pb1 = *(const float4*)(Bp + rowK);

    As[0][lk+0][lr] = pa0.x; As[0][lk+1][lr] = pa0.y; As[0][lk+2][lr] = pa0.z; As[0][lk+3][lr] = pa0.w;
    As[0][lk+0][lr+64] = pa1.x; As[0][lk+1][lr+64] = pa1.y; As[0][lk+2][lr+64] = pa1.z; As[0][lk+3][lr+64] = pa1.w;
    Bs[0][lk+0][lr] = pb0.x; Bs[0][lk+1][lr] = pb0.y; Bs[0][lk+2][lr] = pb0.z; Bs[0][lk+3][lr] = pb0.w;
    Bs[0][lk+0][lr+64] = pb1.x; Bs[0][lk+1][lr+64] = pb1.y; Bs[0][lk+2][lr+64] = pb1.z; Bs[0][lk+3][lr+64] = pb1.w;
    __syncthreads();

    float acc[8][8] = {};
    int buf = 0;

    for (int k0 = 0; k0 < K; k0 += GBK) {
        bool more = (k0 + GBK) < K;
        if (more) {
            pa0 = *(const float4*)(Ap + k0 + GBK);
            pa1 = *(const float4*)(Ap + k0 + GBK + rowK);
            pb0 = *(const float4*)(Bp + k0 + GBK);
            pb1 = *(const float4*)(Bp + k0 + GBK + rowK);
        }

        #pragma unroll
        for (int kk = 0; kk < GBK; kk++) {
            float4 a0 = *(const float4*)&As[buf][kk][ty * 8];
            float4 a1 = *(const float4*)&As[buf][kk][ty * 8 + 4];
            float4 b0 = *(const float4*)&Bs[buf][kk][tx * 8];
            float4 b1 = *(const float4*)&Bs[buf][kk][tx * 8 + 4];
            float av[8] = {a0.x,a0.y,a0.z,a0.w,a1.x,a1.y,a1.z,a1.w};
            float bv[8] = {b0.x,b0.y,b0.z,b0.w,b1.x,b1.y,b1.z,b1.w};
            #pragma unroll
            for (int i = 0; i < 8; i++)
                #pragma unroll
                for (int j = 0; j < 8; j++)
                    acc[i][j] = fmaf(av[i], bv[j], acc[i][j]);
        }

        if (more) {
            int nb = buf ^ 1;
            As[nb][lk+0][lr] = pa0.x; As[nb][lk+1][lr] = pa0.y; As[nb][lk+2][lr] = pa0.z; As[nb][lk+3][lr] = pa0.w;
            As[nb][lk+0][lr+64] = pa1.x; As[nb][lk+1][lr+64] = pa1.y; As[nb][lk+2][lr+64] = pa1.z; As[nb][lk+3][lr+64] = pa1.w;
            Bs[nb][lk+0][lr] = pb0.x; Bs[nb][lk+1][lr] = pb0.y; Bs[nb][lk+2][lr] = pb0.z; Bs[nb][lk+3][lr] = pb0.w;
            Bs[nb][lk+0][lr+64] = pb1.x; Bs[nb][lk+1][lr+64] = pb1.y; Bs[nb][lk+2][lr+64] = pb1.z; Bs[nb][lk+3][lr+64] = pb1.w;
        }
        __syncthreads();
        buf ^= 1;
    }

    // epilogue
    float4 bi0 = *(const float4*)&bias[n0 + tx * 8];
    float4 bi1 = *(const float4*)&bias[n0 + tx * 8 + 4];
    #pragma unroll
    for (int i = 0; i < 8; i++) {
        size_t row = (size_t)(m0 + ty * 8 + i) * N + n0 + tx * 8;
        float4 o0 = make_float4(acc[i][0] + bi0.x, acc[i][1] + bi0.y,
                                acc[i][2] + bi0.z, acc[i][3] + bi0.w);
        float4 o1 = make_float4(acc[i][4] + bi1.x, acc[i][5] + bi1.y,
                                acc[i][6] + bi1.z, acc[i][7] + bi1.w);
        *(float4*)&C[row] = o0;
        *(float4*)&C[row + 4] = o1;
    }
}

// ---------------------------------------------------------------------------
// Flash attention, Br=128 rows x Bc=64 cols per tile, 256 threads, 8x4 micro.
// Smem layouts (d-major for Q/K, t-major for P) so all inner loads are LDS.128.
// Softmax fully in registers via 16-lane shfl reductions.
// Spills unnormalized probs + running max to global for the colsum pass.
// ---------------------------------------------------------------------------
#define QS 132          // Qt stride (128+4)
#define KS 68           // Kt/Vs stride (64+4)
#define PS 132          // Pt stride (128+4)
#define ATTN_SMEM_FLOATS (64*QS + 64*KS + 64*KS + 64*PS)
#define ATTN_SMEM_BYTES (ATTN_SMEM_FLOATS * 4)

__global__ __launch_bounds__(256) void attn_kernel(
    const float* __restrict__ qkv, float* __restrict__ ctx)
{
    extern __shared__ __align__(16) float sm[];
    float* Qt = sm;                  // [64][132]  Qt[d][r]
    float* Kt = Qt + 64 * QS;        // [64][68]   Kt[d][t]
    float* Vs = Kt + 64 * KS;        // [64][68]   Vs[t][d]
    float* Pt = Vs + 64 * KS;        // [64][132]  Pt[t][r]

    const int tid = threadIdx.x;
    const int tx = tid & 15;         // t-col group (4 cols)
    const int ty = tid >> 4;         // row group (8 rows)
    const int sb = blockIdx.x;
    const int h  = blockIdx.y;
    const int b  = blockIdx.z;
    const int s0 = sb * 128;
    const int cta = (b * HEADS + h) * NSB + sb;
    const float scale = 0.125f;

    // load Q tile (transposed into Qt[d][r])
    for (int idx = tid; idx < 128 * 64; idx += 256) {
        int r = idx >> 6, d = idx & 63;
        Qt[d * QS + r] = qkv[((size_t)(s0 + r) * BATCH + b) * F3 + h * HDIM + d];
    }

    float acc[8][4] = {};
    float mrow[8], lrow[8];
    #pragma unroll
    for (int i = 0; i < 8; i++) { mrow[i] = -1e30f; lrow[i] = 0.0f; }
    __syncthreads();

    for (int tb = 0; tb < NTILE; tb++) {
        int t0 = tb * 64;
        // load K (transposed) and V tiles
        for (int idx = tid; idx < 64 * 64; idx += 256) {
            int r = idx >> 6, d = idx & 63;
            const float* base = qkv + ((size_t)(t0 + r) * BATCH + b) * F3 + h * HDIM + d;
            Kt[d * KS + r] = base[EMB];
            Vs[r * KS + d] = base[2 * EMB];
        }
        __syncthreads();

        // S = Q K^T  (8x4 per thread)
        float sreg[8][4] = {};
        #pragma unroll 8
        for (int d = 0; d < 64; d++) {
            float4 a0 = *(const float4*)&Qt[d * QS + ty * 8];
            float4 a1 = *(const float4*)&Qt[d * QS + ty * 8 + 4];
            float4 kf = *(const float4*)&Kt[d * KS + tx * 4];
            float av[8] = {a0.x,a0.y,a0.z,a0.w,a1.x,a1.y,a1.z,a1.w};
            float kv[4] = {kf.x,kf.y,kf.z,kf.w};
            #pragma unroll
            for (int i = 0; i < 8; i++)
                #pragma unroll
                for (int j = 0; j < 4; j++)
                    sreg[i][j] = fmaf(av[i], kv[j], sreg[i][j]);
        }

        // register softmax: per row i, reduce across 16 tx lanes
        #pragma unroll
        for (int i = 0; i < 8; i++) {
            float s0v = sreg[i][0] * scale, s1v = sreg[i][1] * scale;
            float s2v = sreg[i][2] * scale, s3v = sreg[i][3] * scale;
            float tm = fmaxf(fmaxf(s0v, s1v), fmaxf(s2v, s3v));
            #pragma unroll
            for (int off = 8; off >= 1; off >>= 1)
                tm = fmaxf(tm, __shfl_xor_sync(0xffffffffu, tm, off, 16));
            float mnew = fmaxf(mrow[i], tm);
            float corr = __expf(mrow[i] - mnew);
            float p0 = __expf(s0v - mnew), p1 = __expf(s1v - mnew);
            float p2 = __expf(s2v - mnew), p3 = __expf(s3v - mnew);
            float psum = p0 + p1 + p2 + p3;
            #pragma unroll
            for (int off = 8; off >= 1; off >>= 1)
                psum += __shfl_xor_sync(0xffffffffu, psum, off, 16);
            lrow[i] = lrow[i] * corr + psum;
            mrow[i] = mnew;
            #pragma unroll
            for (int j = 0; j < 4; j++) acc[i][j] *= corr;
            sreg[i][0] = p0; sreg[i][1] = p1; sreg[i][2] = p2; sreg[i][3] = p3;
        }

        // write probs to Pt[t][r]
        #pragma unroll
        for (int j = 0; j < 4; j++)
            #pragma unroll
            for (int i = 0; i < 8; i++)
                Pt[(tx * 4 + j) * PS + ty * 8 + i] = sreg[i][j];

        // running max to global (lane tx==0 owns its 8 rows)
        if (tx == 0) {
            float* mdst = g_mrun + ((size_t)cta * NTILE + tb) * 128 + ty * 8;
            #pragma unroll
            for (int i = 0; i < 8; i++) mdst[i] = mrow[i];
        }
        __syncthreads();

        // spill unnormalized probs to global (coalesced float4 copy)
        {
            float* gp = g_ps + (((size_t)cta * NTILE + tb) * 64) * 128;
            for (int u = tid; u < 64 * 32; u += 256) {
                int t = u >> 5, rq = (u & 31) << 2;
                *(float4*)(gp + t * 128 + rq) = *(const float4*)&Pt[t * PS + rq];
            }
        }

        // PV accumulate
        #pragma unroll 8
        for (int t = 0; t < 64; t++) {
            float4 p0 = *(const float4*)&Pt[t * PS + ty * 8];
            float4 p1 = *(const float4*)&Pt[t * PS + ty * 8 + 4];
            float4 vf = *(const float4*)&Vs[t * KS + tx * 4];
            float pv[8] = {p0.x,p0.y,p0.z,p0.w,p1.x,p1.y,p1.z,p1.w};
            float vv[4] = {vf.x,vf.y,vf.z,vf.w};
            #pragma unroll
            for (int i = 0; i < 8; i++)
                #pragma unroll
                for (int j = 0; j < 4; j++)
                    acc[i][j] = fmaf(pv[i], vv[j], acc[i][j]);
        }
        __syncthreads();
    }

    // final l to global
    if (tx == 0) {
        float* ldst = g_lf + (size_t)cta * 128 + ty * 8;
        #pragma unroll
        for (int i = 0; i < 8; i++) ldst[i] = lrow[i];
    }

    // write normalized ctx
    #pragma unroll
    for (int i = 0; i < 8; i++) {
        int r = ty * 8 + i;
        float inv_l = 1.0f / lrow[i];
        float4 o = make_float4(acc[i][0]*inv_l, acc[i][1]*inv_l,
                               acc[i][2]*inv_l, acc[i][3]*inv_l);
        *(float4*)&ctx[((size_t)(s0 + r) * BATCH + b) * EMB + h * HDIM + tx * 4] = o;
    }
}

// ---------------------------------------------------------------------------
// colsum pass: colsum[b][t] += sum_{h,i} ps[cta][tb][t][i] * exp(m_tb[i]-mF[i]) / lF[i]
// ---------------------------------------------------------------------------
__global__ __launch_bounds__(256) void colsum_kernel(float* __restrict__ colsum)
{
    const int sb = blockIdx.x, h = blockIdx.y, b = blockIdx.z;
    const int cta = (b * HEADS + h) * NSB + sb;
    __shared__ float corrs[128];
    __shared__ float csum[64];
    __shared__ float mf_s[128], il_s[128];

    const int tid = threadIdx.x;
    if (tid < 128) {
        mf_s[tid] = g_mrun[((size_t)cta * NTILE + (NTILE - 1)) * 128 + tid];
        il_s[tid] = 1.0f / g_lf[(size_t)cta * 128 + tid];
    }
    const int t = tid & 63;
    const int q = tid >> 6;   // row quarter 0..3

    for (int tb = 0; tb < NTILE; tb++) {
        __syncthreads();
        if (tid < 128)
            corrs[tid] = __expf(g_mrun[((size_t)cta * NTILE + tb) * 128 + tid] - mf_s[tid]) * il_s[tid];
        if (tid < 64) csum[tid] = 0.0f;
        __syncthreads();

        const float* base = g_ps + (((size_t)cta * NTILE + tb) * 64 + t) * 128 + q * 32;
        const float* cr = &corrs[q * 32];
        float part = 0.0f;
        #pragma unroll
        for (int r4 = 0; r4 < 8; r4++) {
            float4 v = *(const float4*)(base + r4 * 4);
            part += v.x * cr[r4*4] + v.y * cr[r4*4+1] + v.z * cr[r4*4+2] + v.w * cr[r4*4+3];
        }
        atomicAdd(&csum[t], part);
        __syncthreads();
        if (tid < 64) atomicAdd(&colsum[b * S_LEN + tb * 64 + t], csum[t]);
    }
}

// ---------------------------------------------------------------------------
// pooled[b,e] = sum_t (colsum[b,t] / (S*H)) * AO[t,b,e]
// ---------------------------------------------------------------------------
__global__ __launch_bounds__(256) void pool_kernel(
    const float* __restrict__ AO, const float* __restrict__ colsum,
    float* __restrict__ out)
{
    int b = blockIdx.y;
    int t0 = blockIdx.x * 64;
    float accv[4] = {0.f, 0.f, 0.f, 0.f};
    const float inv = 1.0f / ((float)S_LEN * (float)HEADS);
    for (int tt = t0; tt < t0 + 64; tt++) {
        float w = colsum[b * S_LEN + tt] * inv;
        const float* row = AO + ((size_t)tt * BATCH + b) * EMB;
        #pragma unroll
        for (int k = 0; k < 4; k++)
            accv[k] = fmaf(w, row[threadIdx.x + k * 256], accv[k]);
    }
    #pragma unroll
    for (int k = 0; k < 4; k++)
        atomicAdd(&out[b * EMB + threadIdx.x + k * 256], accv[k]);
}

// ---------------------------------------------------------------------------
extern "C" void kernel_launch(void* const* d_in, const int* in_sizes, int n_in,
                              void* d_out, int out_size)
{
    const float* x     = (const float*)d_in[0];
    const float* w_in  = (const float*)d_in[1];
    const float* b_in  = (const float*)d_in[2];
    const float* w_out = (const float*)d_in[3];
    const float* b_out = (const float*)d_in[4];
    float* out = (float*)d_out;

    float *qkv_p, *ctx_p, *ao_p, *colsum_p;
    cudaGetSymbolAddress((void**)&qkv_p,    g_qkv);
    cudaGetSymbolAddress((void**)&ctx_p,    g_ctx);
    cudaGetSymbolAddress((void**)&ao_p,     g_ao);
    cudaGetSymbolAddress((void**)&colsum_p, g_colsum);

    cudaFuncSetAttribute(attn_kernel, cudaFuncAttributeMaxDynamicSharedMemorySize,
                         ATTN_SMEM_BYTES);

    zero_kernel<<<32, 256>>>(out);

    sgemm_bias<<<dim3(F3 / GBN, MROWS / GBM), 256>>>(x, w_in, b_in, qkv_p,
                                                     MROWS, F3, EMB);

    attn_kernel<<<dim3(NSB, HEADS, BATCH), 256, ATTN_SMEM_BYTES>>>(qkv_p, ctx_p);

    colsum_kernel<<<dim3(NSB, HEADS, BATCH), 256>>>(colsum_p);

    sgemm_bias<<<dim3(EMB / GBN, MROWS / GBM), 256>>>(ctx_p, w_out, b_out, ao_p,
                                                      MROWS, EMB, EMB);

    pool_kernel<<<dim3(S_LEN / 64, BATCH), 256>>>(ao_p, colsum_p, out);
}

// round 4
// speedup vs baseline: 2.2629x; 1.4382x over previous
#include <cuda_runtime.h>
#include <cuda_bf16.h>
#include <math.h>
#include <stdint.h>

// Problem constants (fixed shapes)
#define S_LEN 1024
#define BATCH 8
#define EMB   1024
#define HEADS 16
#define HDIM  64
#define MROWS (S_LEN * BATCH)   // 8192
#define F3    (3 * EMB)         // 3072
#define NSB   (S_LEN / 128)     // 8 s-blocks per (b,h)
#define NCTA  (BATCH * HEADS * NSB)  // 1024 attention CTAs
#define NTILE 16                // 1024/64 t-tiles

// -------- scratch (__device__ globals; no cudaMalloc allowed) --------
__device__ float g_qkv[MROWS * F3];
__device__ float g_ctx[MROWS * EMB];
__device__ float g_ao [MROWS * EMB];
__device__ float g_colsum[BATCH * S_LEN];
__device__ float g_ps[(size_t)NCTA * NTILE * 64 * 128];
__device__ float g_mrun[NCTA * NTILE * 128];
__device__ float g_lf[NCTA * 128];

// ===========================================================================
// helpers: cp.async + tf32 mma.sync (sm_80+ PTX; works on plain sm_100 target)
// ===========================================================================
__device__ __forceinline__ uint32_t smem_u32(const void* p) {
    return (uint32_t)__cvta_generic_to_shared(p);
}
#define CP_ASYNC16(dst, src) \
    asm volatile("cp.async.cg.shared.global [%0], [%1], 16;" :: "r"(dst), "l"(src))
#define CP_ASYNC_COMMIT() asm volatile("cp.async.commit_group;" ::: "memory")
#define CP_ASYNC_WAIT(n)  asm volatile("cp.async.wait_group %0;" :: "n"(n) : "memory")

__device__ __forceinline__ uint32_t f2tf32(float f) {
    uint32_t u;
    asm("cvt.rna.tf32.f32 %0, %1;" : "=r"(u) : "f"(f));
    return u;
}

__device__ __forceinline__ void mma_tf32(float* c, const uint32_t* a, const uint32_t* b) {
    asm volatile(
        "mma.sync.aligned.m16n8k8.row.col.f32.tf32.tf32.f32 "
        "{%0,%1,%2,%3}, {%4,%5,%6,%7}, {%8,%9}, {%0,%1,%2,%3};"
        : "+f"(c[0]), "+f"(c[1]), "+f"(c[2]), "+f"(c[3])
        : "r"(a[0]), "r"(a[1]), "r"(a[2]), "r"(a[3]), "r"(b[0]), "r"(b[1]));
}

// ===========================================================================
// zero kernel
// ===========================================================================
__global__ void zero_kernel(float* out) {
    int i = blockIdx.x * 256 + threadIdx.x;
    if (i < BATCH * S_LEN) g_colsum[i] = 0.0f;
    if (i < BATCH * EMB)   out[i] = 0.0f;
}

// ===========================================================================
// tf32 tensor-core GEMM: C[m][n] = sum_k A[m][k]*B[n][k] + bias[n]
// 128x128 tile, BK=32, 256 threads (8 warps as 2x4), warp tile 64x32,
// m16n8k8 mma.sync, 3-stage cp.async pipeline.
// SMEM stride 36 floats -> conflict-free fragment loads.
// ===========================================================================
#define TSTAGES 3
#define TBK 32
#define TLDS 36     // padded k-stride (floats)
#define TILE_FLOATS (128 * TLDS)
#define STAGE_BYTES (2 * TILE_FLOATS * 4)   // A + B per stage = 36864
#define GEMM_SMEM (TSTAGES * STAGE_BYTES)   // 110592

__global__ __launch_bounds__(256) void tc_gemm(
    const float* __restrict__ A, const float* __restrict__ B,
    const float* __restrict__ bias, float* __restrict__ C,
    int M, int N, int K)
{
    extern __shared__ __align__(16) float smem[];
    // layout: stage s: A at s*2*TILE_FLOATS, B at s*2*TILE_FLOATS + TILE_FLOATS
    const uint32_t sbase = smem_u32(smem);

    const int tid  = threadIdx.x;
    const int wid  = tid >> 5;
    const int lane = tid & 31;
    const int wr = wid >> 2;        // 0..1  (warp row: 64 m-rows)
    const int wc = wid & 3;         // 0..3  (warp col: 32 n-cols)
    const int qrow = lane >> 2;     // 0..7
    const int qcol = lane & 3;      // 0..3

    const int m0 = blockIdx.y * 128;
    const int n0 = blockIdx.x * 128;
    const int KT = K / TBK;

    // global->smem mapping: row = tid>>1 (0..127), half = tid&1, 4 chunks of 16B
    const int grow = tid >> 1;
    const int ghalf = tid & 1;
    const float* Ag = A + (size_t)(m0 + grow) * K + ghalf * 16;
    const float* Bg = B + (size_t)(n0 + grow) * K + ghalf * 16;
    const uint32_t srowA = sbase + (grow * TLDS + ghalf * 16) * 4;
    const uint32_t srowB = srowA + TILE_FLOATS * 4;

    // prologue: stages 0,1
    #pragma unroll
    for (int p = 0; p < TSTAGES - 1; p++) {
        uint32_t so = (uint32_t)(p * STAGE_BYTES);
        #pragma unroll
        for (int i = 0; i < 4; i++) {
            CP_ASYNC16(srowA + so + i * 16, Ag + p * TBK + i * 4);
            CP_ASYNC16(srowB + so + i * 16, Bg + p * TBK + i * 4);
        }
        CP_ASYNC_COMMIT();
    }

    float acc[4][4][4] = {};

    for (int kt = 0; kt < KT; kt++) {
        if (kt < KT - 1) { CP_ASYNC_WAIT(1); } else { CP_ASYNC_WAIT(0); }
        __syncthreads();

        // prefetch stage kt+2
        if (kt + 2 < KT) {
            uint32_t so = (uint32_t)(((kt + 2) % TSTAGES) * STAGE_BYTES);
            #pragma unroll
            for (int i = 0; i < 4; i++) {
                CP_ASYNC16(srowA + so + i * 16, Ag + (kt + 2) * TBK + i * 4);
                CP_ASYNC16(srowB + so + i * 16, Bg + (kt + 2) * TBK + i * 4);
            }
            CP_ASYNC_COMMIT();
        }

        const float* As = smem + (kt % TSTAGES) * (2 * TILE_FLOATS);
        const float* Bs = As + TILE_FLOATS;

        #pragma unroll
        for (int ks = 0; ks < 4; ks++) {
            const int k0 = ks * 8 + qcol;
            uint32_t afr[4][4];
            uint32_t bfr[4][2];
            #pragma unroll
            for (int mt = 0; mt < 4; mt++) {
                const float* ar = As + (wr * 64 + mt * 16 + qrow) * TLDS;
                afr[mt][0] = f2tf32(ar[k0]);
                afr[mt][1] = f2tf32(ar[8 * TLDS + k0]);
                afr[mt][2] = f2tf32(ar[k0 + 4]);
                afr[mt][3] = f2tf32(ar[8 * TLDS + k0 + 4]);
            }
            #pragma unroll
            for (int nt = 0; nt < 4; nt++) {
                const float* br = Bs + (wc * 32 + nt * 8 + qrow) * TLDS;
                bfr[nt][0] = f2tf32(br[k0]);
                bfr[nt][1] = f2tf32(br[k0 + 4]);
            }
            #pragma unroll
            for (int mt = 0; mt < 4; mt++)
                #pragma unroll
                for (int nt = 0; nt < 4; nt++)
                    mma_tf32(acc[mt][nt], afr[mt], bfr[nt]);
        }
        __syncthreads();
    }

    // epilogue: c0 (r, 2c), c1 (r, 2c+1), c2 (r+8, 2c), c3 (r+8, 2c+1)
    #pragma unroll
    for (int mt = 0; mt < 4; mt++) {
        int row = m0 + wr * 64 + mt * 16 + qrow;
        #pragma unroll
        for (int nt = 0; nt < 4; nt++) {
            int col = n0 + wc * 32 + nt * 8 + 2 * qcol;
            float b0 = bias[col], b1 = bias[col + 1];
            float2 o0 = make_float2(acc[mt][nt][0] + b0, acc[mt][nt][1] + b1);
            float2 o1 = make_float2(acc[mt][nt][2] + b0, acc[mt][nt][3] + b1);
            *(float2*)&C[(size_t)row * N + col] = o0;
            *(float2*)&C[(size_t)(row + 8) * N + col] = o1;
        }
    }
}

// ===========================================================================
// Flash attention (unchanged from R2): fp32, Br=128 x Bc=64, prob spill.
// ===========================================================================
#define QS 132
#define KS 68
#define PS 132
#define ATTN_SMEM_FLOATS (64*QS + 64*KS + 64*KS + 64*PS)
#define ATTN_SMEM_BYTES (ATTN_SMEM_FLOATS * 4)

__global__ __launch_bounds__(256) void attn_kernel(
    const float* __restrict__ qkv, float* __restrict__ ctx)
{
    extern __shared__ __align__(16) float sm[];
    float* Qt = sm;
    float* Kt = Qt + 64 * QS;
    float* Vs = Kt + 64 * KS;
    float* Pt = Vs + 64 * KS;

    const int tid = threadIdx.x;
    const int tx = tid & 15;
    const int ty = tid >> 4;
    const int sb = blockIdx.x;
    const int h  = blockIdx.y;
    const int b  = blockIdx.z;
    const int s0 = sb * 128;
    const int cta = (b * HEADS + h) * NSB + sb;
    const float scale = 0.125f;

    for (int idx = tid; idx < 128 * 64; idx += 256) {
        int r = idx >> 6, d = idx & 63;
        Qt[d * QS + r] = qkv[((size_t)(s0 + r) * BATCH + b) * F3 + h * HDIM + d];
    }

    float acc[8][4] = {};
    float mrow[8], lrow[8];
    #pragma unroll
    for (int i = 0; i < 8; i++) { mrow[i] = -1e30f; lrow[i] = 0.0f; }
    __syncthreads();

    for (int tb = 0; tb < NTILE; tb++) {
        int t0 = tb * 64;
        for (int idx = tid; idx < 64 * 64; idx += 256) {
            int r = idx >> 6, d = idx & 63;
            const float* base = qkv + ((size_t)(t0 + r) * BATCH + b) * F3 + h * HDIM + d;
            Kt[d * KS + r] = base[EMB];
            Vs[r * KS + d] = base[2 * EMB];
        }
        __syncthreads();

        float sreg[8][4] = {};
        #pragma unroll 8
        for (int d = 0; d < 64; d++) {
            float4 a0 = *(const float4*)&Qt[d * QS + ty * 8];
            float4 a1 = *(const float4*)&Qt[d * QS + ty * 8 + 4];
            float4 kf = *(const float4*)&Kt[d * KS + tx * 4];
            float av[8] = {a0.x,a0.y,a0.z,a0.w,a1.x,a1.y,a1.z,a1.w};
            float kv[4] = {kf.x,kf.y,kf.z,kf.w};
            #pragma unroll
            for (int i = 0; i < 8; i++)
                #pragma unroll
                for (int j = 0; j < 4; j++)
                    sreg[i][j] = fmaf(av[i], kv[j], sreg[i][j]);
        }

        #pragma unroll
        for (int i = 0; i < 8; i++) {
            float s0v = sreg[i][0] * scale, s1v = sreg[i][1] * scale;
            float s2v = sreg[i][2] * scale, s3v = sreg[i][3] * scale;
            float tm = fmaxf(fmaxf(s0v, s1v), fmaxf(s2v, s3v));
            #pragma unroll
            for (int off = 8; off >= 1; off >>= 1)
                tm = fmaxf(tm, __shfl_xor_sync(0xffffffffu, tm, off, 16));
            float mnew = fmaxf(mrow[i], tm);
            float corr = __expf(mrow[i] - mnew);
            float p0 = __expf(s0v - mnew), p1 = __expf(s1v - mnew);
            float p2 = __expf(s2v - mnew), p3 = __expf(s3v - mnew);
            float psum = p0 + p1 + p2 + p3;
            #pragma unroll
            for (int off = 8; off >= 1; off >>= 1)
                psum += __shfl_xor_sync(0xffffffffu, psum, off, 16);
            lrow[i] = lrow[i] * corr + psum;
            mrow[i] = mnew;
            #pragma unroll
            for (int j = 0; j < 4; j++) acc[i][j] *= corr;
            sreg[i][0] = p0; sreg[i][1] = p1; sreg[i][2] = p2; sreg[i][3] = p3;
        }

        #pragma unroll
        for (int j = 0; j < 4; j++)
            #pragma unroll
            for (int i = 0; i < 8; i++)
                Pt[(tx * 4 + j) * PS + ty * 8 + i] = sreg[i][j];

        if (tx == 0) {
            float* mdst = g_mrun + ((size_t)cta * NTILE + tb) * 128 + ty * 8;
            #pragma unroll
            for (int i = 0; i < 8; i++) mdst[i] = mrow[i];
        }
        __syncthreads();

        {
            float* gp = g_ps + (((size_t)cta * NTILE + tb) * 64) * 128;
            for (int u = tid; u < 64 * 32; u += 256) {
                int t = u >> 5, rq = (u & 31) << 2;
                *(float4*)(gp + t * 128 + rq) = *(const float4*)&Pt[t * PS + rq];
            }
        }

        #pragma unroll 8
        for (int t = 0; t < 64; t++) {
            float4 p0 = *(const float4*)&Pt[t * PS + ty * 8];
            float4 p1 = *(const float4*)&Pt[t * PS + ty * 8 + 4];
            float4 vf = *(const float4*)&Vs[t * KS + tx * 4];
            float pv[8] = {p0.x,p0.y,p0.z,p0.w,p1.x,p1.y,p1.z,p1.w};
            float vv[4] = {vf.x,vf.y,vf.z,vf.w};
            #pragma unroll
            for (int i = 0; i < 8; i++)
                #pragma unroll
                for (int j = 0; j < 4; j++)
                    acc[i][j] = fmaf(pv[i], vv[j], acc[i][j]);
        }
        __syncthreads();
    }

    if (tx == 0) {
        float* ldst = g_lf + (size_t)cta * 128 + ty * 8;
        #pragma unroll
        for (int i = 0; i < 8; i++) ldst[i] = lrow[i];
    }

    #pragma unroll
    for (int i = 0; i < 8; i++) {
        int r = ty * 8 + i;
        float inv_l = 1.0f / lrow[i];
        float4 o = make_float4(acc[i][0]*inv_l, acc[i][1]*inv_l,
                               acc[i][2]*inv_l, acc[i][3]*inv_l);
        *(float4*)&ctx[((size_t)(s0 + r) * BATCH + b) * EMB + h * HDIM + tx * 4] = o;
    }
}

// ===========================================================================
// colsum pass (unchanged)
// ===========================================================================
__global__ __launch_bounds__(256) void colsum_kernel(float* __restrict__ colsum)
{
    const int sb = blockIdx.x, h = blockIdx.y, b = blockIdx.z;
    const int cta = (b * HEADS + h) * NSB + sb;
    __shared__ float corrs[128];
    __shared__ float csum[64];
    __shared__ float mf_s[128], il_s[128];

    const int tid = threadIdx.x;
    if (tid < 128) {
        mf_s[tid] = g_mrun[((size_t)cta * NTILE + (NTILE - 1)) * 128 + tid];
        il_s[tid] = 1.0f / g_lf[(size_t)cta * 128 + tid];
    }
    const int t = tid & 63;
    const int q = tid >> 6;

    for (int tb = 0; tb < NTILE; tb++) {
        __syncthreads();
        if (tid < 128)
            corrs[tid] = __expf(g_mrun[((size_t)cta * NTILE + tb) * 128 + tid] - mf_s[tid]) * il_s[tid];
        if (tid < 64) csum[tid] = 0.0f;
        __syncthreads();

        const float* base = g_ps + (((size_t)cta * NTILE + tb) * 64 + t) * 128 + q * 32;
        const float* cr = &corrs[q * 32];
        float part = 0.0f;
        #pragma unroll
        for (int r4 = 0; r4 < 8; r4++) {
            float4 v = *(const float4*)(base + r4 * 4);
            part += v.x * cr[r4*4] + v.y * cr[r4*4+1] + v.z * cr[r4*4+2] + v.w * cr[r4*4+3];
        }
        atomicAdd(&csum[t], part);
        __syncthreads();
        if (tid < 64) atomicAdd(&colsum[b * S_LEN + tb * 64 + t], csum[t]);
    }
}

// ===========================================================================
// pooling (unchanged)
// ===========================================================================
__global__ __launch_bounds__(256) void pool_kernel(
    const float* __restrict__ AO, const float* __restrict__ colsum,
    float* __restrict__ out)
{
    int b = blockIdx.y;
    int t0 = blockIdx.x * 64;
    float accv[4] = {0.f, 0.f, 0.f, 0.f};
    const float inv = 1.0f / ((float)S_LEN * (float)HEADS);
    for (int tt = t0; tt < t0 + 64; tt++) {
        float w = colsum[b * S_LEN + tt] * inv;
        const float* row = AO + ((size_t)tt * BATCH + b) * EMB;
        #pragma unroll
        for (int k = 0; k < 4; k++)
            accv[k] = fmaf(w, row[threadIdx.x + k * 256], accv[k]);
    }
    #pragma unroll
    for (int k = 0; k < 4; k++)
        atomicAdd(&out[b * EMB + threadIdx.x + k * 256], accv[k]);
}

// ===========================================================================
extern "C" void kernel_launch(void* const* d_in, const int* in_sizes, int n_in,
                              void* d_out, int out_size)
{
    const float* x     = (const float*)d_in[0];
    const float* w_in  = (const float*)d_in[1];
    const float* b_in  = (const float*)d_in[2];
    const float* w_out = (const float*)d_in[3];
    const float* b_out = (const float*)d_in[4];
    float* out = (float*)d_out;

    float *qkv_p, *ctx_p, *ao_p, *colsum_p;
    cudaGetSymbolAddress((void**)&qkv_p,    g_qkv);
    cudaGetSymbolAddress((void**)&ctx_p,    g_ctx);
    cudaGetSymbolAddress((void**)&ao_p,     g_ao);
    cudaGetSymbolAddress((void**)&colsum_p, g_colsum);

    cudaFuncSetAttribute(attn_kernel, cudaFuncAttributeMaxDynamicSharedMemorySize,
                         ATTN_SMEM_BYTES);
    cudaFuncSetAttribute(tc_gemm, cudaFuncAttributeMaxDynamicSharedMemorySize,
                         GEMM_SMEM);

    zero_kernel<<<32, 256>>>(out);

    // QKV projection (tf32 mma.sync): (8192 x 3072) = x @ w_in^T
    tc_gemm<<<dim3(F3 / 128, MROWS / 128), 256, GEMM_SMEM>>>(
        x, w_in, b_in, qkv_p, MROWS, F3, EMB);

    attn_kernel<<<dim3(NSB, HEADS, BATCH), 256, ATTN_SMEM_BYTES>>>(qkv_p, ctx_p);

    colsum_kernel<<<dim3(NSB, HEADS, BATCH), 256>>>(colsum_p);

    // out projection (tf32 mma.sync): (8192 x 1024) = ctx @ w_out^T
    tc_gemm<<<dim3(EMB / 128, MROWS / 128), 256, GEMM_SMEM>>>(
        ctx_p, w_out, b_out, ao_p, MROWS, EMB, EMB);

    pool_kernel<<<dim3(S_LEN / 64, BATCH), 256>>>(ao_p, colsum_p, out);
}

// round 5
// speedup vs baseline: 3.0689x; 1.3562x over previous
#include <cuda_runtime.h>
#include <cuda_bf16.h>
#include <math.h>
#include <stdint.h>

// Problem constants (fixed shapes)
#define S_LEN 1024
#define BATCH 8
#define EMB   1024
#define HEADS 16
#define HDIM  64
#define MROWS (S_LEN * BATCH)   // 8192
#define F3    (3 * EMB)         // 3072
#define NSB   (S_LEN / 128)     // 8 s-blocks per (b,h)
#define NTILE 16                // 1024/64 t-tiles

// -------- scratch (__device__ globals; no cudaMalloc allowed) --------
__device__ float g_qkv[MROWS * F3];
__device__ float g_ctx[MROWS * EMB];
__device__ float g_ao [MROWS * EMB];
__device__ float g_colsum[BATCH * S_LEN];

// ===========================================================================
// helpers: cp.async + tf32 mma.sync
// ===========================================================================
__device__ __forceinline__ uint32_t smem_u32(const void* p) {
    return (uint32_t)__cvta_generic_to_shared(p);
}
#define CP_ASYNC16(dst, src) \
    asm volatile("cp.async.cg.shared.global [%0], [%1], 16;" :: "r"(dst), "l"(src))
#define CP_ASYNC_COMMIT() asm volatile("cp.async.commit_group;" ::: "memory")
#define CP_ASYNC_WAIT(n)  asm volatile("cp.async.wait_group %0;" :: "n"(n) : "memory")

__device__ __forceinline__ uint32_t f2tf32(float f) {
    uint32_t u;
    asm("cvt.rna.tf32.f32 %0, %1;" : "=r"(u) : "f"(f));
    return u;
}
// tf32-rounded value kept as fp32 bit pattern (valid fp32)
__device__ __forceinline__ float tf32f(float f) {
    return __uint_as_float(f2tf32(f));
}

__device__ __forceinline__ void mma_tf32(float* c, const uint32_t* a, const uint32_t* b) {
    asm volatile(
        "mma.sync.aligned.m16n8k8.row.col.f32.tf32.tf32.f32 "
        "{%0,%1,%2,%3}, {%4,%5,%6,%7}, {%8,%9}, {%0,%1,%2,%3};"
        : "+f"(c[0]), "+f"(c[1]), "+f"(c[2]), "+f"(c[3])
        : "r"(a[0]), "r"(a[1]), "r"(a[2]), "r"(a[3]), "r"(b[0]), "r"(b[1]));
}

// ===========================================================================
// zero kernel
// ===========================================================================
__global__ void zero_kernel(float* out) {
    int i = blockIdx.x * 256 + threadIdx.x;
    if (i < BATCH * S_LEN) g_colsum[i] = 0.0f;
    if (i < BATCH * EMB)   out[i] = 0.0f;
}

// ===========================================================================
// tf32 tensor-core GEMM (unchanged from R4 passing version)
// ===========================================================================
#define TSTAGES 3
#define TBK 32
#define TLDS 36
#define TILE_FLOATS (128 * TLDS)
#define STAGE_BYTES (2 * TILE_FLOATS * 4)
#define GEMM_SMEM (TSTAGES * STAGE_BYTES)

__global__ __launch_bounds__(256) void tc_gemm(
    const float* __restrict__ A, const float* __restrict__ B,
    const float* __restrict__ bias, float* __restrict__ C,
    int M, int N, int K)
{
    extern __shared__ __align__(16) float smem[];
    const uint32_t sbase = smem_u32(smem);

    const int tid  = threadIdx.x;
    const int wid  = tid >> 5;
    const int lane = tid & 31;
    const int wr = wid >> 2;
    const int wc = wid & 3;
    const int qrow = lane >> 2;
    const int qcol = lane & 3;

    const int m0 = blockIdx.y * 128;
    const int n0 = blockIdx.x * 128;
    const int KT = K / TBK;

    const int grow = tid >> 1;
    const int ghalf = tid & 1;
    const float* Ag = A + (size_t)(m0 + grow) * K + ghalf * 16;
    const float* Bg = B + (size_t)(n0 + grow) * K + ghalf * 16;
    const uint32_t srowA = sbase + (grow * TLDS + ghalf * 16) * 4;
    const uint32_t srowB = srowA + TILE_FLOATS * 4;

    #pragma unroll
    for (int p = 0; p < TSTAGES - 1; p++) {
        uint32_t so = (uint32_t)(p * STAGE_BYTES);
        #pragma unroll
        for (int i = 0; i < 4; i++) {
            CP_ASYNC16(srowA + so + i * 16, Ag + p * TBK + i * 4);
            CP_ASYNC16(srowB + so + i * 16, Bg + p * TBK + i * 4);
        }
        CP_ASYNC_COMMIT();
    }

    float acc[4][4][4] = {};

    for (int kt = 0; kt < KT; kt++) {
        if (kt < KT - 1) { CP_ASYNC_WAIT(1); } else { CP_ASYNC_WAIT(0); }
        __syncthreads();

        if (kt + 2 < KT) {
            uint32_t so = (uint32_t)(((kt + 2) % TSTAGES) * STAGE_BYTES);
            #pragma unroll
            for (int i = 0; i < 4; i++) {
                CP_ASYNC16(srowA + so + i * 16, Ag + (kt + 2) * TBK + i * 4);
                CP_ASYNC16(srowB + so + i * 16, Bg + (kt + 2) * TBK + i * 4);
            }
            CP_ASYNC_COMMIT();
        }

        const float* As = smem + (kt % TSTAGES) * (2 * TILE_FLOATS);
        const float* Bs = As + TILE_FLOATS;

        #pragma unroll
        for (int ks = 0; ks < 4; ks++) {
            const int k0 = ks * 8 + qcol;
            uint32_t afr[4][4];
            uint32_t bfr[4][2];
            #pragma unroll
            for (int mt = 0; mt < 4; mt++) {
                const float* ar = As + (wr * 64 + mt * 16 + qrow) * TLDS;
                afr[mt][0] = f2tf32(ar[k0]);
                afr[mt][1] = f2tf32(ar[8 * TLDS + k0]);
                afr[mt][2] = f2tf32(ar[k0 + 4]);
                afr[mt][3] = f2tf32(ar[8 * TLDS + k0 + 4]);
            }
            #pragma unroll
            for (int nt = 0; nt < 4; nt++) {
                const float* br = Bs + (wc * 32 + nt * 8 + qrow) * TLDS;
                bfr[nt][0] = f2tf32(br[k0]);
                bfr[nt][1] = f2tf32(br[k0 + 4]);
            }
            #pragma unroll
            for (int mt = 0; mt < 4; mt++)
                #pragma unroll
                for (int nt = 0; nt < 4; nt++)
                    mma_tf32(acc[mt][nt], afr[mt], bfr[nt]);
        }
        __syncthreads();
    }

    #pragma unroll
    for (int mt = 0; mt < 4; mt++) {
        int row = m0 + wr * 64 + mt * 16 + qrow;
        #pragma unroll
        for (int nt = 0; nt < 4; nt++) {
            int col = n0 + wc * 32 + nt * 8 + 2 * qcol;
            float b0 = bias[col], b1 = bias[col + 1];
            float2 o0 = make_float2(acc[mt][nt][0] + b0, acc[mt][nt][1] + b1);
            float2 o1 = make_float2(acc[mt][nt][2] + b0, acc[mt][nt][3] + b1);
            *(float2*)&C[(size_t)row * N + col] = o0;
            *(float2*)&C[(size_t)(row + 8) * N + col] = o1;
        }
    }
}

// ===========================================================================
// Flash attention, tf32 mma.sync. Br=128, Bc=64, 8 warps x 16-row warp tiles.
// Pass 1: flash (QK^T + PV on tensor cores), ctx written.
// Pass 2: recompute QK^T, exact probs with final (m,l) from registers,
//         column sums -> g_colsum. No global spill of probs.
// ===========================================================================
#define QD 68
#define KD 68
#define VD 72
#define PD 68
#define ATTN_SMEM ((128*QD + 64*KD + 64*VD + 128*PD + 64) * 4)   // 105728 B

__global__ __launch_bounds__(256, 2) void attn_kernel(
    const float* __restrict__ qkv, float* __restrict__ ctx,
    float* __restrict__ colsum)
{
    extern __shared__ __align__(16) float sm[];
    float* Qs = sm;                    // [128][QD] tf32, pre-scaled
    float* Ks = Qs + 128 * QD;         // [64][KD]  tf32
    float* Vs = Ks + 64 * KD;          // [64][VD]  tf32
    float* Ps = Vs + 64 * VD;          // [128][PD] tf32 probs
    float* csum_s = Ps + 128 * PD;     // [64]

    const int tid  = threadIdx.x;
    const int wid  = tid >> 5;
    const int lane = tid & 31;
    const int qrow = lane >> 2;       // 0..7
    const int q    = lane & 3;        // 0..3
    const int sb = blockIdx.x, h = blockIdx.y, b = blockIdx.z;
    const int s0 = sb * 128;
    const int R0 = wid * 16 + qrow;   // warp's row block; rows R0, R0+8

    // ---- load Q (scaled by 1/8, tf32-rounded) ----
    for (int idx = tid; idx < 128 * 16; idx += 256) {
        int row = idx >> 4, c = idx & 15;
        float4 v = *(const float4*)&qkv[((size_t)(s0 + row) * BATCH + b) * F3 + h * HDIM + c * 4];
        float4 o = make_float4(tf32f(v.x * 0.125f), tf32f(v.y * 0.125f),
                               tf32f(v.z * 0.125f), tf32f(v.w * 0.125f));
        *(float4*)&Qs[row * QD + c * 4] = o;
    }

    float m0 = -1e30f, m1 = -1e30f, l0 = 0.0f, l1 = 0.0f;
    float acc[8][4] = {};
    __syncthreads();

    // ================= pass 1: flash =================
    for (int tb = 0; tb < NTILE; tb++) {
        const int t0 = tb * 64;
        // load K,V tile (tf32-rounded)
        for (int idx = tid; idx < 64 * 16; idx += 256) {
            int row = idx >> 4, c = idx & 15;
            const float* base = &qkv[((size_t)(t0 + row) * BATCH + b) * F3 + h * HDIM + c * 4];
            float4 kv = *(const float4*)(base + EMB);
            float4 vv = *(const float4*)(base + 2 * EMB);
            *(float4*)&Ks[row * KD + c * 4] =
                make_float4(tf32f(kv.x), tf32f(kv.y), tf32f(kv.z), tf32f(kv.w));
            *(float4*)&Vs[row * VD + c * 4] =
                make_float4(tf32f(vv.x), tf32f(vv.y), tf32f(vv.z), tf32f(vv.w));
        }
        __syncthreads();

        // S = Q K^T (scaled), 16x64 per warp
        float sf[8][4] = {};
        #pragma unroll
        for (int ks = 0; ks < 8; ks++) {
            const int kq = ks * 8 + q;
            uint32_t a[4];
            a[0] = __float_as_uint(Qs[R0 * QD + kq]);
            a[1] = __float_as_uint(Qs[(R0 + 8) * QD + kq]);
            a[2] = __float_as_uint(Qs[R0 * QD + kq + 4]);
            a[3] = __float_as_uint(Qs[(R0 + 8) * QD + kq + 4]);
            #pragma unroll
            for (int nt = 0; nt < 8; nt++) {
                uint32_t bb[2];
                bb[0] = __float_as_uint(Ks[(nt * 8 + qrow) * KD + kq]);
                bb[1] = __float_as_uint(Ks[(nt * 8 + qrow) * KD + kq + 4]);
                mma_tf32(sf[nt], a, bb);
            }
        }

        // online softmax (rows R0 -> sf[nt][0..1], R0+8 -> sf[nt][2..3])
        {
            float tm0 = -1e30f, tm1 = -1e30f;
            #pragma unroll
            for (int nt = 0; nt < 8; nt++) {
                tm0 = fmaxf(tm0, fmaxf(sf[nt][0], sf[nt][1]));
                tm1 = fmaxf(tm1, fmaxf(sf[nt][2], sf[nt][3]));
            }
            tm0 = fmaxf(tm0, __shfl_xor_sync(0xffffffffu, tm0, 1));
            tm0 = fmaxf(tm0, __shfl_xor_sync(0xffffffffu, tm0, 2));
            tm1 = fmaxf(tm1, __shfl_xor_sync(0xffffffffu, tm1, 1));
            tm1 = fmaxf(tm1, __shfl_xor_sync(0xffffffffu, tm1, 2));
            float mn0 = fmaxf(m0, tm0), mn1 = fmaxf(m1, tm1);
            float c0 = __expf(m0 - mn0), c1 = __expf(m1 - mn1);
            float rs0 = 0.0f, rs1 = 0.0f;
            #pragma unroll
            for (int nt = 0; nt < 8; nt++) {
                sf[nt][0] = __expf(sf[nt][0] - mn0);
                sf[nt][1] = __expf(sf[nt][1] - mn0);
                sf[nt][2] = __expf(sf[nt][2] - mn1);
                sf[nt][3] = __expf(sf[nt][3] - mn1);
                rs0 += sf[nt][0] + sf[nt][1];
                rs1 += sf[nt][2] + sf[nt][3];
                // store probs (tf32) for PV
                *(float2*)&Ps[R0 * PD + nt * 8 + 2 * q] =
                    make_float2(tf32f(sf[nt][0]), tf32f(sf[nt][1]));
                *(float2*)&Ps[(R0 + 8) * PD + nt * 8 + 2 * q] =
                    make_float2(tf32f(sf[nt][2]), tf32f(sf[nt][3]));
            }
            rs0 += __shfl_xor_sync(0xffffffffu, rs0, 1);
            rs0 += __shfl_xor_sync(0xffffffffu, rs0, 2);
            rs1 += __shfl_xor_sync(0xffffffffu, rs1, 1);
            rs1 += __shfl_xor_sync(0xffffffffu, rs1, 2);
            l0 = l0 * c0 + rs0; m0 = mn0;
            l1 = l1 * c1 + rs1; m1 = mn1;
            #pragma unroll
            for (int nt = 0; nt < 8; nt++) {
                acc[nt][0] *= c0; acc[nt][1] *= c0;
                acc[nt][2] *= c1; acc[nt][3] *= c1;
            }
        }
        __syncwarp();

        // ctx += P @ V  (k-dim = t)
        #pragma unroll
        for (int ks = 0; ks < 8; ks++) {
            const int kq = ks * 8 + q;
            uint32_t a[4];
            a[0] = __float_as_uint(Ps[R0 * PD + kq]);
            a[1] = __float_as_uint(Ps[(R0 + 8) * PD + kq]);
            a[2] = __float_as_uint(Ps[R0 * PD + kq + 4]);
            a[3] = __float_as_uint(Ps[(R0 + 8) * PD + kq + 4]);
            #pragma unroll
            for (int nt = 0; nt < 8; nt++) {
                uint32_t bb[2];
                bb[0] = __float_as_uint(Vs[kq * VD + nt * 8 + qrow]);
                bb[1] = __float_as_uint(Vs[(kq + 4) * VD + nt * 8 + qrow]);
                mma_tf32(acc[nt], a, bb);
            }
        }
        __syncthreads();
    }

    // normalize + write ctx
    const float inv0 = 1.0f / l0, inv1 = 1.0f / l1;
    #pragma unroll
    for (int nt = 0; nt < 8; nt++) {
        size_t base0 = ((size_t)(s0 + R0) * BATCH + b) * EMB + h * HDIM + nt * 8 + 2 * q;
        size_t base1 = ((size_t)(s0 + R0 + 8) * BATCH + b) * EMB + h * HDIM + nt * 8 + 2 * q;
        *(float2*)&ctx[base0] = make_float2(acc[nt][0] * inv0, acc[nt][1] * inv0);
        *(float2*)&ctx[base1] = make_float2(acc[nt][2] * inv1, acc[nt][3] * inv1);
    }

    // ================= pass 2: column sums =================
    for (int tb = 0; tb < NTILE; tb++) {
        const int t0 = tb * 64;
        __syncthreads();   // Ks reuse + csum flush from previous tile done
        for (int idx = tid; idx < 64 * 16; idx += 256) {
            int row = idx >> 4, c = idx & 15;
            const float* base = &qkv[((size_t)(t0 + row) * BATCH + b) * F3 + h * HDIM + c * 4];
            float4 kv = *(const float4*)(base + EMB);
            *(float4*)&Ks[row * KD + c * 4] =
                make_float4(tf32f(kv.x), tf32f(kv.y), tf32f(kv.z), tf32f(kv.w));
        }
        if (tid < 64) csum_s[tid] = 0.0f;
        __syncthreads();

        float sf[8][4] = {};
        #pragma unroll
        for (int ks = 0; ks < 8; ks++) {
            const int kq = ks * 8 + q;
            uint32_t a[4];
            a[0] = __float_as_uint(Qs[R0 * QD + kq]);
            a[1] = __float_as_uint(Qs[(R0 + 8) * QD + kq]);
            a[2] = __float_as_uint(Qs[R0 * QD + kq + 4]);
            a[3] = __float_as_uint(Qs[(R0 + 8) * QD + kq + 4]);
            #pragma unroll
            for (int nt = 0; nt < 8; nt++) {
                uint32_t bb[2];
                bb[0] = __float_as_uint(Ks[(nt * 8 + qrow) * KD + kq]);
                bb[1] = __float_as_uint(Ks[(nt * 8 + qrow) * KD + kq + 4]);
                mma_tf32(sf[nt], a, bb);
            }
        }

        #pragma unroll
        for (int nt = 0; nt < 8; nt++) {
            float p0 = __expf(sf[nt][0] - m0) * inv0;
            float p1 = __expf(sf[nt][1] - m0) * inv0;
            float p2 = __expf(sf[nt][2] - m1) * inv1;
            float p3 = __expf(sf[nt][3] - m1) * inv1;
            float v0 = p0 + p2, v1 = p1 + p3;
            #pragma unroll
            for (int off = 4; off <= 16; off <<= 1) {
                v0 += __shfl_xor_sync(0xffffffffu, v0, off);
                v1 += __shfl_xor_sync(0xffffffffu, v1, off);
            }
            if (qrow == 0) {
                atomicAdd(&csum_s[nt * 8 + 2 * q], v0);
                atomicAdd(&csum_s[nt * 8 + 2 * q + 1], v1);
            }
        }
        __syncthreads();
        if (tid < 64) atomicAdd(&colsum[b * S_LEN + t0 + tid], csum_s[tid]);
    }
}

// ===========================================================================
// pooling (unchanged)
// ===========================================================================
__global__ __launch_bounds__(256) void pool_kernel(
    const float* __restrict__ AO, const float* __restrict__ colsum,
    float* __restrict__ out)
{
    int b = blockIdx.y;
    int t0 = blockIdx.x * 64;
    float accv[4] = {0.f, 0.f, 0.f, 0.f};
    const float inv = 1.0f / ((float)S_LEN * (float)HEADS);
    for (int tt = t0; tt < t0 + 64; tt++) {
        float w = colsum[b * S_LEN + tt] * inv;
        const float* row = AO + ((size_t)tt * BATCH + b) * EMB;
        #pragma unroll
        for (int k = 0; k < 4; k++)
            accv[k] = fmaf(w, row[threadIdx.x + k * 256], accv[k]);
    }
    #pragma unroll
    for (int k = 0; k < 4; k++)
        atomicAdd(&out[b * EMB + threadIdx.x + k * 256], accv[k]);
}

// ===========================================================================
extern "C" void kernel_launch(void* const* d_in, const int* in_sizes, int n_in,
                              void* d_out, int out_size)
{
    const float* x     = (const float*)d_in[0];
    const float* w_in  = (const float*)d_in[1];
    const float* b_in  = (const float*)d_in[2];
    const float* w_out = (const float*)d_in[3];
    const float* b_out = (const float*)d_in[4];
    float* out = (float*)d_out;

    float *qkv_p, *ctx_p, *ao_p, *colsum_p;
    cudaGetSymbolAddress((void**)&qkv_p,    g_qkv);
    cudaGetSymbolAddress((void**)&ctx_p,    g_ctx);
    cudaGetSymbolAddress((void**)&ao_p,     g_ao);
    cudaGetSymbolAddress((void**)&colsum_p, g_colsum);

    cudaFuncSetAttribute(attn_kernel, cudaFuncAttributeMaxDynamicSharedMemorySize,
                         ATTN_SMEM);
    cudaFuncSetAttribute(tc_gemm, cudaFuncAttributeMaxDynamicSharedMemorySize,
                         GEMM_SMEM);

    zero_kernel<<<32, 256>>>(out);

    // QKV projection (tf32 mma.sync): (8192 x 3072) = x @ w_in^T
    tc_gemm<<<dim3(F3 / 128, MROWS / 128), 256, GEMM_SMEM>>>(
        x, w_in, b_in, qkv_p, MROWS, F3, EMB);

    // attention: ctx + colsum, no spill
    attn_kernel<<<dim3(NSB, HEADS, BATCH), 256, ATTN_SMEM>>>(
        qkv_p, ctx_p, colsum_p);

    // out projection (tf32 mma.sync): (8192 x 1024) = ctx @ w_out^T
    tc_gemm<<<dim3(EMB / 128, MROWS / 128), 256, GEMM_SMEM>>>(
        ctx_p, w_out, b_out, ao_p, MROWS, EMB, EMB);

    pool_kernel<<<dim3(S_LEN / 64, BATCH), 256>>>(ao_p, colsum_p, out);
}